// round 2
// baseline (speedup 1.0000x reference)
#include <cuda_runtime.h>

#define NB 8
#define NQ 128
#define NK 512
#define ND 512     // d_q == d_kv
#define DA 256     // d_attn
#define QB 4       // queries per CTA in attn_main

#define SCALE2LOG2E 2.8853900817779268f   // 2*log2(e)
#define LOG2E       1.4426950408889634f

// ---------------- scratch (static device globals; no cudaMalloc) ---------------
__device__ float g_Wt[1024 * DA];           // W transposed: [d (1024)][a (256)]
__device__ float g_qp[NB * NQ * DA];        // q_proj + bias
__device__ float g_kp[NB * NK * DA];        // k_proj  [m (4096)][a (256)]
__device__ float g_kpt[DA * NB * NK];       // k_proj transposed+scaled [a][m]
__device__ float g_kvpart[NB * 32 * ND];    // partial kv sums (32 segs of 16 k)

__device__ __forceinline__ float ex2(float x) {
    float r; asm("ex2.approx.f32 %0, %1;" : "=f"(r) : "f"(x)); return r;
}
__device__ __forceinline__ float rcp(float x) {
    float r; asm("rcp.approx.f32 %0, %1;" : "=f"(r) : "f"(x)); return r;
}

// ---------------- W transpose: W(256 x 1024) -> Wt(1024 x 256) ----------------
__global__ void transpose_w(const float* __restrict__ W) {
    __shared__ float tile[32][33];
    const int d0 = blockIdx.x * 32;
    const int a0 = blockIdx.y * 32;
    const int tx = threadIdx.x, ty = threadIdx.y;  // (32, 8)
#pragma unroll
    for (int j = 0; j < 32; j += 8)
        tile[ty + j][tx] = W[(a0 + ty + j) * 1024 + d0 + tx];
    __syncthreads();
#pragma unroll
    for (int j = 0; j < 32; j += 8)
        g_Wt[(d0 + ty + j) * DA + a0 + tx] = tile[tx][ty + j];
}

// ---------------- projection GEMM: Out[m,a] = sum_d X[m,d] * Wt[doff+d][a] ----
__global__ __launch_bounds__(256) void proj_gemm(
    const float* __restrict__ X, const float* __restrict__ bias,
    float* __restrict__ Out, int doff, int rows_per_b,
    const int* __restrict__ lens)
{
    const int a0 = blockIdx.x * 64;
    const int m0 = blockIdx.y * 64;
    const int b  = m0 / rows_per_b;
    const int r0 = m0 % rows_per_b;
    if (r0 >= lens[b]) return;   // whole tile masked

    __shared__ float As[16][68];
    __shared__ float Bs[16][68];
    const int tid = threadIdx.x;
    const int tx = tid & 15, ty = tid >> 4;

    const int ar = tid >> 2;
    const int ac = (tid & 3) * 4;
    const int bd = tid >> 4;
    const int bf = (tid & 15) * 4;

    float acc[4][4] = {};

    for (int d0 = 0; d0 < ND; d0 += 16) {
        float4 av = *(const float4*)(X + (m0 + ar) * ND + d0 + ac);
        float4 bv = *(const float4*)(g_Wt + (doff + d0 + bd) * DA + a0 + bf);
        As[ac + 0][ar] = av.x; As[ac + 1][ar] = av.y;
        As[ac + 2][ar] = av.z; As[ac + 3][ar] = av.w;
        *(float4*)&Bs[bd][bf] = bv;
        __syncthreads();
#pragma unroll
        for (int kk = 0; kk < 16; kk++) {
            float4 afv = *(const float4*)&As[kk][ty * 4];
            float4 bfv = *(const float4*)&Bs[kk][tx * 4];
            float aa[4] = {afv.x, afv.y, afv.z, afv.w};
            float bb[4] = {bfv.x, bfv.y, bfv.z, bfv.w};
#pragma unroll
            for (int i = 0; i < 4; i++)
#pragma unroll
                for (int j = 0; j < 4; j++)
                    acc[i][j] += aa[i] * bb[j];
        }
        __syncthreads();
    }

    float badd[4] = {0.f, 0.f, 0.f, 0.f};
    if (bias) {
        badd[0] = bias[a0 + tx * 4 + 0];
        badd[1] = bias[a0 + tx * 4 + 1];
        badd[2] = bias[a0 + tx * 4 + 2];
        badd[3] = bias[a0 + tx * 4 + 3];
    }
#pragma unroll
    for (int i = 0; i < 4; i++) {
        const int m = m0 + ty * 4 + i;
        float4 o;
        o.x = acc[i][0] + badd[0];
        o.y = acc[i][1] + badd[1];
        o.z = acc[i][2] + badd[2];
        o.w = acc[i][3] + badd[3];
        *(float4*)(Out + m * DA + a0 + tx * 4) = o;
    }
}

// ---------------- kp transpose + pre-scale: g_kpt[a][m] = SCALE * g_kp[m][a] ---
__global__ void transpose_kp() {
    __shared__ float tile[32][33];
    const int m0 = blockIdx.x * 32;      // 128 tiles over m = 4096
    const int a0 = blockIdx.y * 32;      // 8 tiles over a = 256
    const int tx = threadIdx.x, ty = threadIdx.y;  // (32, 8)
#pragma unroll
    for (int j = 0; j < 32; j += 8)
        tile[ty + j][tx] = g_kp[(m0 + ty + j) * DA + a0 + tx];
    __syncthreads();
#pragma unroll
    for (int j = 0; j < 32; j += 8)
        g_kpt[(size_t)(a0 + ty + j) * (NB * NK) + m0 + tx] =
            tile[tx][ty + j] * SCALE2LOG2E;
}

// ---------------- kv partial sums for masked-q rows (32 segs of 16) ------------
__global__ void kv_partial(const float* __restrict__ kv) {
    const int b = blockIdx.x, seg = blockIdx.y;   // (8, 32)
    const int d = threadIdx.x;                    // 512
    const float* p = kv + (size_t)(b * NK + seg * 16) * ND + d;
    float s = 0.f;
#pragma unroll
    for (int k = 0; k < 16; k++) s += p[k * ND];
    g_kvpart[(b * 32 + seg) * ND + d] = s;
}

// ---------------- main fused kernel: score + softmax + attn@kv ------------------
// One CTA = QB(4) queries. Score phase: k-per-lane over transposed kp, no shfl.
__global__ __launch_bounds__(256) void attn_main(
    const float* __restrict__ kv, const float* __restrict__ vvec,
    const int* __restrict__ qlen_p, const int* __restrict__ klen_p,
    float* __restrict__ out)
{
    const int b  = blockIdx.y;
    const int q0 = blockIdx.x * QB;
    const int tid = threadIdx.x;
    const int w = tid >> 5, lane = tid & 31;
    const int qlen = qlen_p[b];
    const int klen = klen_p[b];

    // --- fully masked CTA: uniform attention over all NK keys -------------------
    if (q0 >= qlen) {
        float u0 = 0.f, u1 = 0.f;
#pragma unroll 8
        for (int g = 0; g < 32; g++) {
            u0 += g_kvpart[(b * 32 + g) * ND + tid];
            u1 += g_kvpart[(b * 32 + g) * ND + 256 + tid];
        }
        u0 *= (1.0f / (float)NK);
        u1 *= (1.0f / (float)NK);
#pragma unroll
        for (int qi = 0; qi < QB; qi++) {
            float* orow = out + (size_t)(b * NQ + q0 + qi) * ND;
            orow[tid] = u0; orow[tid + 256] = u1;
        }
        return;
    }

    __shared__ float  sct[NK * QB];      // sct[k*QB + qi] : scores then probs
    __shared__ float4 qp4[DA];           // per-a packed qp for the 4 queries
    __shared__ float2 v2s[DA];           // (v[a], 2*v[a])
    __shared__ float  redmax[QB][2];
    __shared__ float  redsum[QB][2];

    // --- stage qp (scaled) and v ------------------------------------------------
    for (int i = tid; i < DA; i += 256) {
        float vv = vvec[i];
        v2s[i] = make_float2(vv, 2.0f * vv);
        float4 t;
        const float* qpb = g_qp + (size_t)(b * NQ + q0) * DA + i;
        t.x = qpb[0 * DA] * SCALE2LOG2E;
        t.y = qpb[1 * DA] * SCALE2LOG2E;
        t.z = qpb[2 * DA] * SCALE2LOG2E;
        t.w = qpb[3 * DA] * SCALE2LOG2E;
        qp4[i] = t;
    }
    __syncthreads();

    // --- score phase: warp w owns k chunks [w*32, w*32+32) and +256 -------------
#pragma unroll
    for (int ch = 0; ch < 2; ch++) {
        const int kbase = ch * 256 + w * 32;
        if (kbase >= klen) continue;
        const int k = kbase + lane;
        const float* kpcol = g_kpt + (size_t)b * NK + k;  // stride NB*NK per a
        float s0 = 0.f, s1 = 0.f, s2 = 0.f, s3 = 0.f;
#pragma unroll 4
        for (int a = 0; a < DA; a++) {
            const float kpv = kpcol[(size_t)a * (NB * NK)];
            const float4 qq = qp4[a];
            const float2 vv = v2s[a];
            float r0 = rcp(1.0f + ex2(qq.x + kpv));
            float r1 = rcp(1.0f + ex2(qq.y + kpv));
            float r2 = rcp(1.0f + ex2(qq.z + kpv));
            float r3 = rcp(1.0f + ex2(qq.w + kpv));
            s0 += vv.x - vv.y * r0;
            s1 += vv.x - vv.y * r1;
            s2 += vv.x - vv.y * r2;
            s3 += vv.x - vv.y * r3;
        }
        float* sp = &sct[k * QB];
        sp[0] = s0; sp[1] = s1; sp[2] = s2; sp[3] = s3;
    }
    __syncthreads();

    // --- softmax: warp w handles query (w&3), k-half (w>>2) ---------------------
    {
        const int q = w & 3;
        const int half = w >> 2;
        const int kb = half * 256;
        float lmax = -1e30f;
#pragma unroll
        for (int i = 0; i < 8; i++) {
            const int k = kb + i * 32 + lane;
            if (k < klen) lmax = fmaxf(lmax, sct[k * QB + q]);
        }
#pragma unroll
        for (int o = 16; o; o >>= 1)
            lmax = fmaxf(lmax, __shfl_xor_sync(0xffffffffu, lmax, o));
        if (lane == 0) redmax[q][half] = lmax;
    }
    __syncthreads();
    {
        const int q = w & 3;
        const int half = w >> 2;
        const int kb = half * 256;
        const float m = fmaxf(redmax[q][0], redmax[q][1]);
        float lsum = 0.f;
#pragma unroll
        for (int i = 0; i < 8; i++) {
            const int k = kb + i * 32 + lane;
            float e = 0.f;
            if (k < klen) e = ex2((sct[k * QB + q] - m) * LOG2E);
            sct[k * QB + q] = e;
            lsum += e;
        }
#pragma unroll
        for (int o = 16; o; o >>= 1)
            lsum += __shfl_xor_sync(0xffffffffu, lsum, o);
        if (lane == 0) redsum[q][half] = lsum;
    }
    __syncthreads();

    // --- AV: out[qi][d] = sum_k p[qi][k] * kv[k][d]; thread owns d=tid, tid+256 -
    const float* kvb = kv + (size_t)b * NK * ND;
    float a00 = 0.f, a01 = 0.f, a10 = 0.f, a11 = 0.f;
    float a20 = 0.f, a21 = 0.f, a30 = 0.f, a31 = 0.f;
    int k = 0;
    for (; k + 4 <= klen; k += 4) {
#pragma unroll
        for (int u = 0; u < 4; u++) {
            const float4 p = *(const float4*)&sct[(k + u) * QB];
            const float x0 = kvb[(size_t)(k + u) * ND + tid];
            const float x1 = kvb[(size_t)(k + u) * ND + 256 + tid];
            a00 += p.x * x0; a01 += p.x * x1;
            a10 += p.y * x0; a11 += p.y * x1;
            a20 += p.z * x0; a21 += p.z * x1;
            a30 += p.w * x0; a31 += p.w * x1;
        }
    }
    for (; k < klen; k++) {
        const float4 p = *(const float4*)&sct[k * QB];
        const float x0 = kvb[(size_t)k * ND + tid];
        const float x1 = kvb[(size_t)k * ND + 256 + tid];
        a00 += p.x * x0; a01 += p.x * x1;
        a10 += p.y * x0; a11 += p.y * x1;
        a20 += p.z * x0; a21 += p.z * x1;
        a30 += p.w * x0; a31 += p.w * x1;
    }

    // --- epilogue ---------------------------------------------------------------
    const int nact = qlen - q0;   // >= 1 here; queries qi < nact are active
    float accs[QB][2] = {{a00,a01},{a10,a11},{a20,a21},{a30,a31}};
#pragma unroll
    for (int qi = 0; qi < QB; qi++) {
        if (qi < nact) {
            const float Z = redsum[qi][0] + redsum[qi][1];
            const float inv = __fdividef(1.0f, Z);
            float* orow = out + (size_t)(b * NQ + q0 + qi) * ND;
            orow[tid]       = accs[qi][0] * inv;
            orow[tid + 256] = accs[qi][1] * inv;
        }
    }
    if (nact < QB) {   // some masked queries in this CTA
        float u0 = 0.f, u1 = 0.f;
#pragma unroll 8
        for (int g = 0; g < 32; g++) {
            u0 += g_kvpart[(b * 32 + g) * ND + tid];
            u1 += g_kvpart[(b * 32 + g) * ND + 256 + tid];
        }
        u0 *= (1.0f / (float)NK);
        u1 *= (1.0f / (float)NK);
#pragma unroll
        for (int qi = 0; qi < QB; qi++) {
            if (qi >= nact) {
                float* orow = out + (size_t)(b * NQ + q0 + qi) * ND;
                orow[tid] = u0; orow[tid + 256] = u1;
            }
        }
    }
}

// ---------------- launch --------------------------------------------------------
extern "C" void kernel_launch(void* const* d_in, const int* in_sizes, int n_in,
                              void* d_out, int out_size)
{
    const float* query = (const float*)d_in[0];
    const float* kv    = (const float*)d_in[1];
    const float* W     = (const float*)d_in[2];
    const float* bias  = (const float*)d_in[3];
    const float* v     = (const float*)d_in[4];
    const int*   qlen  = (const int*)d_in[5];
    const int*   klen  = (const int*)d_in[6];
    float* out = (float*)d_out;

    float *qp, *kp;
    cudaGetSymbolAddress((void**)&qp, g_qp);
    cudaGetSymbolAddress((void**)&kp, g_kp);

    transpose_w<<<dim3(32, 8), dim3(32, 8)>>>(W);
    proj_gemm<<<dim3(DA / 64, (NB * NQ) / 64), 256>>>(query, bias, qp, 0,   NQ, qlen);
    proj_gemm<<<dim3(DA / 64, (NB * NK) / 64), 256>>>(kv,    nullptr, kp, 512, NK, klen);
    transpose_kp<<<dim3((NB * NK) / 32, DA / 32), dim3(32, 8)>>>();
    kv_partial<<<dim3(NB, 32), ND>>>(kv);
    attn_main<<<dim3(NQ / QB, NB), 256>>>(kv, v, qlen, klen, out);
}

// round 3
// speedup vs baseline: 1.2300x; 1.2300x over previous
#include <cuda_runtime.h>

#define NB 8
#define NQ 128
#define NK 512
#define ND 512     // d_q == d_kv
#define DA 256     // d_attn
#define QB 4       // queries per CTA in attn_main
#define NM (NB * NK)   // 4096 total k rows

#define SCALE2LOG2E 2.8853900817779268f   // 2*log2(e)
#define LOG2E       1.4426950408889634f

// ---------------- scratch (static device globals; no cudaMalloc) ---------------
__device__ float g_Wt[1024 * DA];           // W transposed: [d (1024)][a (256)]
__device__ float g_qp[NB * NQ * DA];        // (q_proj + bias) * 2log2e
__device__ float g_kpt[DA * NM];            // k_proj transposed+scaled [a][m]
__device__ float g_kvpart[NB * 32 * ND];    // partial kv sums (32 segs of 16 k)

__device__ __forceinline__ float ex2(float x) {
    float r; asm("ex2.approx.f32 %0, %1;" : "=f"(r) : "f"(x)); return r;
}
__device__ __forceinline__ float rcp(float x) {
    float r; asm("rcp.approx.f32 %0, %1;" : "=f"(r) : "f"(x)); return r;
}

// ---------------- prep: W transpose (blocks 0..255) + kv partials (256..511) ---
__global__ __launch_bounds__(256) void prep(const float* __restrict__ W,
                                            const float* __restrict__ kv)
{
    __shared__ float tile[32][33];
    if (blockIdx.x < 256) {
        const int t  = blockIdx.x;
        const int d0 = (t & 31) * 32;
        const int a0 = (t >> 5) * 32;
        const int tx = threadIdx.x & 31, ty = threadIdx.x >> 5;  // (32, 8)
#pragma unroll
        for (int j = 0; j < 32; j += 8)
            tile[ty + j][tx] = W[(a0 + ty + j) * 1024 + d0 + tx];
        __syncthreads();
#pragma unroll
        for (int j = 0; j < 32; j += 8)
            g_Wt[(d0 + ty + j) * DA + a0 + tx] = tile[tx][ty + j];
    } else {
        const int s = blockIdx.x - 256;
        const int b = s >> 5, seg = s & 31;
        const float2* p = (const float2*)(kv + (size_t)(b * NK + seg * 16) * ND)
                          + threadIdx.x;
        float2 acc = make_float2(0.f, 0.f);
#pragma unroll
        for (int k = 0; k < 16; k++) {
            float2 v = p[k * (ND / 2)];
            acc.x += v.x; acc.y += v.y;
        }
        ((float2*)(g_kvpart + (size_t)(b * 32 + seg) * ND))[threadIdx.x] = acc;
    }
}

// ---------------- projection GEMM ----------------------------------------------
// mode 0: g_qp[m][a]  = (X@Wt[0:512] + bias) * SCALE    (m = b*NQ + q)
// mode 1: g_kpt[a][m] = (X@Wt[512:1024]) * SCALE        (m = b*NK + k, transposed)
__global__ __launch_bounds__(256) void proj_gemm(
    const float* __restrict__ X, const float* __restrict__ bias,
    int doff, int rows_per_b, const int* __restrict__ lens, int mode)
{
    const int a0 = blockIdx.x * 64;
    const int m0 = blockIdx.y * 64;
    const int b  = m0 / rows_per_b;
    const int r0 = m0 % rows_per_b;
    if (r0 >= lens[b]) return;   // whole tile masked (outputs never read)

    __shared__ float As[16][68];
    __shared__ float Bs[16][68];
    const int tid = threadIdx.x;
    const int tx = tid & 15, ty = tid >> 4;

    const int ar = tid >> 2;
    const int ac = (tid & 3) * 4;
    const int bd = tid >> 4;
    const int bf = (tid & 15) * 4;

    float acc[4][4] = {};

    for (int d0 = 0; d0 < ND; d0 += 16) {
        float4 av = *(const float4*)(X + (size_t)(m0 + ar) * ND + d0 + ac);
        float4 bv = *(const float4*)(g_Wt + (size_t)(doff + d0 + bd) * DA + a0 + bf);
        As[ac + 0][ar] = av.x; As[ac + 1][ar] = av.y;
        As[ac + 2][ar] = av.z; As[ac + 3][ar] = av.w;
        *(float4*)&Bs[bd][bf] = bv;
        __syncthreads();
#pragma unroll
        for (int kk = 0; kk < 16; kk++) {
            float4 afv = *(const float4*)&As[kk][ty * 4];
            float4 bfv = *(const float4*)&Bs[kk][tx * 4];
            float aa[4] = {afv.x, afv.y, afv.z, afv.w};
            float bb[4] = {bfv.x, bfv.y, bfv.z, bfv.w};
#pragma unroll
            for (int i = 0; i < 4; i++)
#pragma unroll
                for (int j = 0; j < 4; j++)
                    acc[i][j] += aa[i] * bb[j];
        }
        __syncthreads();
    }

    if (mode == 0) {
        float badd[4];
        badd[0] = bias[a0 + tx * 4 + 0];
        badd[1] = bias[a0 + tx * 4 + 1];
        badd[2] = bias[a0 + tx * 4 + 2];
        badd[3] = bias[a0 + tx * 4 + 3];
#pragma unroll
        for (int i = 0; i < 4; i++) {
            const int m = m0 + ty * 4 + i;
            float4 o;
            o.x = (acc[i][0] + badd[0]) * SCALE2LOG2E;
            o.y = (acc[i][1] + badd[1]) * SCALE2LOG2E;
            o.z = (acc[i][2] + badd[2]) * SCALE2LOG2E;
            o.w = (acc[i][3] + badd[3]) * SCALE2LOG2E;
            *(float4*)(g_qp + (size_t)m * DA + a0 + tx * 4) = o;
        }
    } else {
        // transposed store: kpt[a][m], 4 consecutive m per float4
#pragma unroll
        for (int j = 0; j < 4; j++) {
            const int a = a0 + tx * 4 + j;
            float4 o;
            o.x = acc[0][j] * SCALE2LOG2E;
            o.y = acc[1][j] * SCALE2LOG2E;
            o.z = acc[2][j] * SCALE2LOG2E;
            o.w = acc[3][j] * SCALE2LOG2E;
            *(float4*)(g_kpt + (size_t)a * NM + m0 + ty * 4) = o;
        }
    }
}

// ---------------- main fused kernel: score + softmax + attn@kv ------------------
// grid (NB, NQ/QB): batch-major so heavy-batch CTAs spread across SMs.
__global__ __launch_bounds__(256) void attn_main(
    const float* __restrict__ kv, const float* __restrict__ vvec,
    const int* __restrict__ qlen_p, const int* __restrict__ klen_p,
    float* __restrict__ out)
{
    const int b  = blockIdx.x;
    const int q0 = blockIdx.y * QB;
    const int tid = threadIdx.x;
    const int w = tid >> 5, lane = tid & 31;
    const int qlen = qlen_p[b];
    const int klen = klen_p[b];

    // --- fully masked CTA: uniform attention over all NK keys -------------------
    if (q0 >= qlen) {
        float2 u = make_float2(0.f, 0.f);
#pragma unroll 8
        for (int g = 0; g < 32; g++) {
            float2 t = ((const float2*)(g_kvpart + (size_t)(b * 32 + g) * ND))[tid];
            u.x += t.x; u.y += t.y;
        }
        u.x *= (1.0f / (float)NK);
        u.y *= (1.0f / (float)NK);
#pragma unroll
        for (int qi = 0; qi < QB; qi++)
            ((float2*)(out + (size_t)(b * NQ + q0 + qi) * ND))[tid] = u;
        return;
    }

    __shared__ float  sct[NK * QB];      // sct[k*QB + qi] : scores then probs
    __shared__ float4 qp4[DA];           // per-a packed (pre-scaled) qp, 4 queries
    __shared__ float2 v2s[DA];           // (v[a], 2*v[a])
    __shared__ float  redmax[QB][2];
    __shared__ float  redsum[QB][2];

    // --- stage qp and v ---------------------------------------------------------
    for (int i = tid; i < DA; i += 256) {
        float vv = vvec[i];
        v2s[i] = make_float2(vv, 2.0f * vv);
        const float* qpb = g_qp + (size_t)(b * NQ + q0) * DA + i;
        float4 t;
        t.x = qpb[0 * DA];
        t.y = qpb[1 * DA];
        t.z = qpb[2 * DA];
        t.w = qpb[3 * DA];
        qp4[i] = t;
    }
    __syncthreads();

    // --- score phase: warp w owns k = [w*32, w*32+32) and +256 ------------------
#pragma unroll
    for (int ch = 0; ch < 2; ch++) {
        const int kbase = ch * 256 + w * 32;
        if (kbase >= klen) continue;
        const int k = kbase + lane;
        const float* kpcol = g_kpt + (size_t)b * NK + k;  // stride NM per a
        float s0 = 0.f, s1 = 0.f, s2 = 0.f, s3 = 0.f;
        for (int ab = 0; ab < DA; ab += 8) {
            float kpv[8];
#pragma unroll
            for (int u = 0; u < 8; u++)
                kpv[u] = kpcol[(size_t)(ab + u) * NM];   // MLP=8 batched loads
#pragma unroll
            for (int u = 0; u < 8; u++) {
                const float4 qq = qp4[ab + u];
                const float2 vv = v2s[ab + u];
                float r0 = rcp(1.0f + ex2(qq.x + kpv[u]));
                float r1 = rcp(1.0f + ex2(qq.y + kpv[u]));
                float r2 = rcp(1.0f + ex2(qq.z + kpv[u]));
                float r3 = rcp(1.0f + ex2(qq.w + kpv[u]));
                s0 += vv.x - vv.y * r0;
                s1 += vv.x - vv.y * r1;
                s2 += vv.x - vv.y * r2;
                s3 += vv.x - vv.y * r3;
            }
        }
        float* sp = &sct[k * QB];
        sp[0] = s0; sp[1] = s1; sp[2] = s2; sp[3] = s3;
    }
    __syncthreads();

    // --- softmax: warp w handles query (w&3), k-half (w>>2) ---------------------
    {
        const int q = w & 3;
        const int kb = (w >> 2) * 256;
        float lmax = -1e30f;
#pragma unroll
        for (int i = 0; i < 8; i++) {
            const int k = kb + i * 32 + lane;
            if (k < klen) lmax = fmaxf(lmax, sct[k * QB + q]);
        }
#pragma unroll
        for (int o = 16; o; o >>= 1)
            lmax = fmaxf(lmax, __shfl_xor_sync(0xffffffffu, lmax, o));
        if (lane == 0) redmax[q][w >> 2] = lmax;
    }
    __syncthreads();
    {
        const int q = w & 3;
        const int kb = (w >> 2) * 256;
        const float m = fmaxf(redmax[q][0], redmax[q][1]);
        float lsum = 0.f;
#pragma unroll
        for (int i = 0; i < 8; i++) {
            const int k = kb + i * 32 + lane;
            float e = 0.f;
            if (k < klen) e = ex2((sct[k * QB + q] - m) * LOG2E);
            sct[k * QB + q] = e;
            lsum += e;
        }
#pragma unroll
        for (int o = 16; o; o >>= 1)
            lsum += __shfl_xor_sync(0xffffffffu, lsum, o);
        if (lane == 0) redsum[q][w >> 2] = lsum;
    }
    __syncthreads();

    // --- AV: out[qi][d] = sum_k p[qi][k]*kv[k][d]; thread owns d = 2tid, 2tid+1 -
    const float2* kvb2 = (const float2*)(kv + (size_t)b * NK * ND);
    float2 A0 = {0,0}, A1 = {0,0}, A2 = {0,0}, A3 = {0,0};
    int k = 0;
    for (; k + 4 <= klen; k += 4) {
#pragma unroll
        for (int u = 0; u < 4; u++) {
            const float4 p = *(const float4*)&sct[(k + u) * QB];
            const float2 x = kvb2[(size_t)(k + u) * (ND / 2) + tid];
            A0.x += p.x * x.x; A0.y += p.x * x.y;
            A1.x += p.y * x.x; A1.y += p.y * x.y;
            A2.x += p.z * x.x; A2.y += p.z * x.y;
            A3.x += p.w * x.x; A3.y += p.w * x.y;
        }
    }
    for (; k < klen; k++) {
        const float4 p = *(const float4*)&sct[k * QB];
        const float2 x = kvb2[(size_t)k * (ND / 2) + tid];
        A0.x += p.x * x.x; A0.y += p.x * x.y;
        A1.x += p.y * x.x; A1.y += p.y * x.y;
        A2.x += p.z * x.x; A2.y += p.z * x.y;
        A3.x += p.w * x.x; A3.y += p.w * x.y;
    }

    // --- epilogue ---------------------------------------------------------------
    const int nact = qlen - q0;   // >= 1 here
    float2 accs[QB] = {A0, A1, A2, A3};
#pragma unroll
    for (int qi = 0; qi < QB; qi++) {
        if (qi < nact) {
            const float inv = __fdividef(1.0f, redsum[qi][0] + redsum[qi][1]);
            float2 o = make_float2(accs[qi].x * inv, accs[qi].y * inv);
            ((float2*)(out + (size_t)(b * NQ + q0 + qi) * ND))[tid] = o;
        }
    }
    if (nact < QB) {
        float2 u = make_float2(0.f, 0.f);
#pragma unroll 8
        for (int g = 0; g < 32; g++) {
            float2 t = ((const float2*)(g_kvpart + (size_t)(b * 32 + g) * ND))[tid];
            u.x += t.x; u.y += t.y;
        }
        u.x *= (1.0f / (float)NK);
        u.y *= (1.0f / (float)NK);
#pragma unroll
        for (int qi = 0; qi < QB; qi++)
            if (qi >= nact)
                ((float2*)(out + (size_t)(b * NQ + q0 + qi) * ND))[tid] = u;
    }
}

// ---------------- launch --------------------------------------------------------
extern "C" void kernel_launch(void* const* d_in, const int* in_sizes, int n_in,
                              void* d_out, int out_size)
{
    const float* query = (const float*)d_in[0];
    const float* kv    = (const float*)d_in[1];
    const float* W     = (const float*)d_in[2];
    const float* bias  = (const float*)d_in[3];
    const float* v     = (const float*)d_in[4];
    const int*   qlen  = (const int*)d_in[5];
    const int*   klen  = (const int*)d_in[6];
    float* out = (float*)d_out;

    prep<<<512, 256>>>(W, kv);
    proj_gemm<<<dim3(DA / 64, (NB * NQ) / 64), 256>>>(query, bias, 0,   NQ, qlen, 0);
    proj_gemm<<<dim3(DA / 64, (NB * NK) / 64), 256>>>(kv,    bias, 512, NK, klen, 1);
    attn_main<<<dim3(NB, NQ / QB), 256>>>(kv, v, qlen, klen, out);
}

// round 4
// speedup vs baseline: 1.3166x; 1.0704x over previous
#include <cuda_runtime.h>

#define NB 8
#define NQ 128
#define NK 512
#define ND 512         // d_q == d_kv
#define DA 256         // d_attn
#define NM (NB * NK)   // 4096 total k rows

#define SCALE2LOG2E 2.8853900817779268f   // 2*log2(e)
#define LOG2E       1.4426950408889634f

// ---------------- scratch (static device globals; no cudaMalloc) ---------------
__device__ float g_Wt[1024 * DA];           // W transposed: [d (1024)][a (256)]
__device__ float g_qp[NB * NQ * DA];        // (q_proj + bias) * 2log2e
__device__ float g_kpt[DA * NM];            // k_proj transposed+scaled [a][m]
__device__ float g_kvpart[NB * 32 * ND];    // partial kv sums (32 segs of 16 k)
__device__ float g_sc[NB * NQ * NK];        // scores -> exp'd probs
__device__ float g_iz[NB * NQ];             // 1/Z per (b,q)
__device__ float g_vsum;                    // sum of v

__device__ __forceinline__ float ex2(float x) {
    float r; asm("ex2.approx.f32 %0, %1;" : "=f"(r) : "f"(x)); return r;
}
__device__ __forceinline__ float rcp(float x) {
    float r; asm("rcp.approx.f32 %0, %1;" : "=f"(r) : "f"(x)); return r;
}

// ---------------- prep: Wt (0..255) + kv partials (256..511) + vsum (512) ------
__global__ __launch_bounds__(256) void prep(const float* __restrict__ W,
                                            const float* __restrict__ kv,
                                            const float* __restrict__ v)
{
    if (blockIdx.x < 256) {
        __shared__ float tile[32][33];
        const int t  = blockIdx.x;
        const int d0 = (t & 31) * 32;
        const int a0 = (t >> 5) * 32;
        const int tx = threadIdx.x & 31, ty = threadIdx.x >> 5;  // (32, 8)
#pragma unroll
        for (int j = 0; j < 32; j += 8)
            tile[ty + j][tx] = W[(a0 + ty + j) * 1024 + d0 + tx];
        __syncthreads();
#pragma unroll
        for (int j = 0; j < 32; j += 8)
            g_Wt[(d0 + ty + j) * DA + a0 + tx] = tile[tx][ty + j];
    } else if (blockIdx.x < 512) {
        const int s = blockIdx.x - 256;
        const int b = s >> 5, seg = s & 31;
        const float2* p = (const float2*)(kv + (size_t)(b * NK + seg * 16) * ND)
                          + threadIdx.x;
        float2 acc = make_float2(0.f, 0.f);
#pragma unroll
        for (int k = 0; k < 16; k++) {
            float2 t = p[k * (ND / 2)];
            acc.x += t.x; acc.y += t.y;
        }
        ((float2*)(g_kvpart + (size_t)(b * 32 + seg) * ND))[threadIdx.x] = acc;
    } else {
        __shared__ float red[256];
        red[threadIdx.x] = v[threadIdx.x];
        __syncthreads();
        for (int o = 128; o; o >>= 1) {
            if (threadIdx.x < o) red[threadIdx.x] += red[threadIdx.x + o];
            __syncthreads();
        }
        if (threadIdx.x == 0) g_vsum = red[0];
    }
}

// ---------------- projection GEMM ----------------------------------------------
// mode 0: g_qp[m][a]  = (X@Wt[0:512] + bias) * SCALE    (m = b*NQ + q)
// mode 1: g_kpt[a][m] = (X@Wt[512:1024]) * SCALE        (m = b*NK + k, transposed)
__global__ __launch_bounds__(256) void proj_gemm(
    const float* __restrict__ X, const float* __restrict__ bias,
    int doff, int rows_per_b, const int* __restrict__ lens, int mode)
{
    const int a0 = blockIdx.x * 64;
    const int m0 = blockIdx.y * 64;
    const int b  = m0 / rows_per_b;
    const int r0 = m0 % rows_per_b;
    if (r0 >= lens[b]) return;   // whole tile masked (outputs never read)

    __shared__ float As[16][68];
    __shared__ float Bs[16][68];
    const int tid = threadIdx.x;
    const int tx = tid & 15, ty = tid >> 4;

    const int ar = tid >> 2;
    const int ac = (tid & 3) * 4;
    const int bd = tid >> 4;
    const int bf = (tid & 15) * 4;

    float acc[4][4] = {};

    for (int d0 = 0; d0 < ND; d0 += 16) {
        float4 av = *(const float4*)(X + (size_t)(m0 + ar) * ND + d0 + ac);
        float4 bv = *(const float4*)(g_Wt + (size_t)(doff + d0 + bd) * DA + a0 + bf);
        As[ac + 0][ar] = av.x; As[ac + 1][ar] = av.y;
        As[ac + 2][ar] = av.z; As[ac + 3][ar] = av.w;
        *(float4*)&Bs[bd][bf] = bv;
        __syncthreads();
#pragma unroll
        for (int kk = 0; kk < 16; kk++) {
            float4 afv = *(const float4*)&As[kk][ty * 4];
            float4 bfv = *(const float4*)&Bs[kk][tx * 4];
            float aa[4] = {afv.x, afv.y, afv.z, afv.w};
            float bb[4] = {bfv.x, bfv.y, bfv.z, bfv.w};
#pragma unroll
            for (int i = 0; i < 4; i++)
#pragma unroll
                for (int j = 0; j < 4; j++)
                    acc[i][j] += aa[i] * bb[j];
        }
        __syncthreads();
    }

    if (mode == 0) {
        float badd[4];
        badd[0] = bias[a0 + tx * 4 + 0];
        badd[1] = bias[a0 + tx * 4 + 1];
        badd[2] = bias[a0 + tx * 4 + 2];
        badd[3] = bias[a0 + tx * 4 + 3];
#pragma unroll
        for (int i = 0; i < 4; i++) {
            const int m = m0 + ty * 4 + i;
            float4 o;
            o.x = (acc[i][0] + badd[0]) * SCALE2LOG2E;
            o.y = (acc[i][1] + badd[1]) * SCALE2LOG2E;
            o.z = (acc[i][2] + badd[2]) * SCALE2LOG2E;
            o.w = (acc[i][3] + badd[3]) * SCALE2LOG2E;
            *(float4*)(g_qp + (size_t)m * DA + a0 + tx * 4) = o;
        }
    } else {
#pragma unroll
        for (int j = 0; j < 4; j++) {
            const int a = a0 + tx * 4 + j;
            float4 o;
            o.x = acc[0][j] * SCALE2LOG2E;
            o.y = acc[1][j] * SCALE2LOG2E;
            o.z = acc[2][j] * SCALE2LOG2E;
            o.w = acc[3][j] * SCALE2LOG2E;
            *(float4*)(g_kpt + (size_t)a * NM + m0 + ty * 4) = o;
        }
    }
}

// ---------------- K1: scores. grid (NB, NQ/4, NK/64); thread = one (k, qi) -----
__global__ __launch_bounds__(256) void score_kernel(
    const float* __restrict__ vvec,
    const int* __restrict__ qlen_p, const int* __restrict__ klen_p)
{
    const int b  = blockIdx.x;
    const int q0 = blockIdx.y * 4;
    const int k0 = blockIdx.z * 64;
    if (q0 >= qlen_p[b] || k0 >= klen_p[b]) return;

    const int tid = threadIdx.x;
    const int kk = tid & 63;
    const int qi = tid >> 6;

    __shared__ float qsm[4][DA];
    __shared__ float vsm[DA];
    for (int i = tid; i < 4 * DA; i += 256)
        qsm[i >> 8][i & 255] = g_qp[(size_t)(b * NQ + q0 + (i >> 8)) * DA + (i & 255)];
    for (int i = tid; i < DA; i += 256) vsm[i] = vvec[i];
    __syncthreads();

    const float* kpcol = g_kpt + (size_t)b * NK + k0 + kk;   // stride NM per a
    const float* qrow  = qsm[qi];
    float s = 0.f;
    for (int a = 0; a < DA; a += 8) {
        float kpv[8];
#pragma unroll
        for (int u = 0; u < 8; u++)
            kpv[u] = kpcol[(size_t)(a + u) * NM];            // MLP=8 batched
#pragma unroll
        for (int u = 0; u < 8; u++) {
            float r = rcp(1.0f + ex2(qrow[a + u] + kpv[u]));
            s = fmaf(vsm[a + u], r, s);
        }
    }
    // score = sum_a v_a * (1 - 2 r_a) = vsum - 2*s
    g_sc[(size_t)(b * NQ + q0 + qi) * NK + k0 + kk] = g_vsum - 2.0f * s;
}

// ---------------- K2: softmax per row. grid (NB, NQ/8); warp = one q row -------
__global__ __launch_bounds__(256) void softmax_kernel(
    const int* __restrict__ qlen_p, const int* __restrict__ klen_p)
{
    const int b = blockIdx.x;
    const int q = blockIdx.y * 8 + (threadIdx.x >> 5);
    const int lane = threadIdx.x & 31;
    float* row = g_sc + (size_t)(b * NQ + q) * NK;

    if (q >= qlen_p[b]) {
        // masked row: uniform over ALL k -> e = 1, Z = NK
        const float4 one = make_float4(1.f, 1.f, 1.f, 1.f);
#pragma unroll
        for (int i = 0; i < 4; i++)
            *(float4*)(row + i * 128 + lane * 4) = one;
        if (lane == 0) g_iz[b * NQ + q] = 1.0f / (float)NK;
        return;
    }

    const int klen = klen_p[b];
    float4 vals[4];
    float lmax = -1e30f;
#pragma unroll
    for (int i = 0; i < 4; i++) {
        const int kb = i * 128 + lane * 4;
        vals[i] = *(const float4*)(row + kb);
        if (kb + 0 < klen) lmax = fmaxf(lmax, vals[i].x);
        if (kb + 1 < klen) lmax = fmaxf(lmax, vals[i].y);
        if (kb + 2 < klen) lmax = fmaxf(lmax, vals[i].z);
        if (kb + 3 < klen) lmax = fmaxf(lmax, vals[i].w);
    }
#pragma unroll
    for (int o = 16; o; o >>= 1)
        lmax = fmaxf(lmax, __shfl_xor_sync(0xffffffffu, lmax, o));

    float lsum = 0.f;
#pragma unroll
    for (int i = 0; i < 4; i++) {
        const int kb = i * 128 + lane * 4;
        float4 e;
        e.x = (kb + 0 < klen) ? ex2((vals[i].x - lmax) * LOG2E) : 0.f;
        e.y = (kb + 1 < klen) ? ex2((vals[i].y - lmax) * LOG2E) : 0.f;
        e.z = (kb + 2 < klen) ? ex2((vals[i].z - lmax) * LOG2E) : 0.f;
        e.w = (kb + 3 < klen) ? ex2((vals[i].w - lmax) * LOG2E) : 0.f;
        lsum += e.x + e.y + e.z + e.w;
        *(float4*)(row + kb) = e;
    }
#pragma unroll
    for (int o = 16; o; o >>= 1)
        lsum += __shfl_xor_sync(0xffffffffu, lsum, o);
    if (lane == 0) g_iz[b * NQ + q] = __fdividef(1.0f, lsum);
}

// ---------------- K3: AV. grid (NB, NQ/4, ND/128); 256 thr, k split in 2 -------
__global__ __launch_bounds__(256) void av_kernel(
    const float* __restrict__ kv,
    const int* __restrict__ qlen_p, const int* __restrict__ klen_p,
    float* __restrict__ out)
{
    const int b  = blockIdx.x;
    const int q0 = blockIdx.y * 4;
    const int dc = blockIdx.z;
    const int tid = threadIdx.x;
    const int dl = tid & 127;
    const int kh = tid >> 7;
    const int d  = dc * 128 + dl;
    const int qlen = qlen_p[b];

    __shared__ float part[4][128];

    if (q0 >= qlen) {
        // fully masked tile: uniform mean over all NK keys
        float u = 0.f;
#pragma unroll
        for (int g = kh * 16; g < kh * 16 + 16; g++)
            u += g_kvpart[(size_t)(b * 32 + g) * ND + d];
        if (kh == 1) part[0][dl] = u;
        __syncthreads();
        if (kh == 0) {
            u = (u + part[0][dl]) * (1.0f / (float)NK);
#pragma unroll
            for (int qi = 0; qi < 4; qi++)
                out[(size_t)(b * NQ + q0 + qi) * ND + d] = u;
        }
        return;
    }

    const int klen = klen_p[b];
    const int kmax = (q0 + 4 <= qlen) ? klen : NK;  // partial tile spans all k
    const float* scb = g_sc + (size_t)(b * NQ + q0) * NK;
    const float* kvp = kv + (size_t)b * NK * ND + d;

    float a0 = 0.f, a1 = 0.f, a2 = 0.f, a3 = 0.f;
    int k = kh;
    for (; k + 6 < kmax; k += 8) {
        float x[4];
#pragma unroll
        for (int u = 0; u < 4; u++) x[u] = kvp[(size_t)(k + 2 * u) * ND];
#pragma unroll
        for (int u = 0; u < 4; u++) {
            const int kc = k + 2 * u;
            a0 = fmaf(scb[kc],          x[u], a0);
            a1 = fmaf(scb[NK + kc],     x[u], a1);
            a2 = fmaf(scb[2 * NK + kc], x[u], a2);
            a3 = fmaf(scb[3 * NK + kc], x[u], a3);
        }
    }
    for (; k < kmax; k += 2) {
        const float x = kvp[(size_t)k * ND];
        a0 = fmaf(scb[k],          x, a0);
        a1 = fmaf(scb[NK + k],     x, a1);
        a2 = fmaf(scb[2 * NK + k], x, a2);
        a3 = fmaf(scb[3 * NK + k], x, a3);
    }

    if (kh == 1) {
        part[0][dl] = a0; part[1][dl] = a1;
        part[2][dl] = a2; part[3][dl] = a3;
    }
    __syncthreads();
    if (kh == 0) {
        a0 += part[0][dl]; a1 += part[1][dl];
        a2 += part[2][dl]; a3 += part[3][dl];
        const float* izp = g_iz + b * NQ + q0;
        out[(size_t)(b * NQ + q0 + 0) * ND + d] = a0 * izp[0];
        out[(size_t)(b * NQ + q0 + 1) * ND + d] = a1 * izp[1];
        out[(size_t)(b * NQ + q0 + 2) * ND + d] = a2 * izp[2];
        out[(size_t)(b * NQ + q0 + 3) * ND + d] = a3 * izp[3];
    }
}

// ---------------- launch --------------------------------------------------------
extern "C" void kernel_launch(void* const* d_in, const int* in_sizes, int n_in,
                              void* d_out, int out_size)
{
    const float* query = (const float*)d_in[0];
    const float* kv    = (const float*)d_in[1];
    const float* W     = (const float*)d_in[2];
    const float* bias  = (const float*)d_in[3];
    const float* v     = (const float*)d_in[4];
    const int*   qlen  = (const int*)d_in[5];
    const int*   klen  = (const int*)d_in[6];
    float* out = (float*)d_out;

    prep<<<513, 256>>>(W, kv, v);
    proj_gemm<<<dim3(DA / 64, (NB * NQ) / 64), 256>>>(query, bias, 0,   NQ, qlen, 0);
    proj_gemm<<<dim3(DA / 64, (NB * NK) / 64), 256>>>(kv,    bias, 512, NK, klen, 1);
    score_kernel<<<dim3(NB, NQ / 4, NK / 64), 256>>>(v, qlen, klen);
    softmax_kernel<<<dim3(NB, NQ / 8), 256>>>(qlen, klen);
    av_kernel<<<dim3(NB, NQ / 4, ND / 128), 256>>>(kv, qlen, klen, out);
}

// round 7
// speedup vs baseline: 1.8052x; 1.3712x over previous
#include <cuda_runtime.h>

#define NB 8
#define NQ 128
#define NK 512
#define ND 512         // d_q == d_kv
#define DA 256         // d_attn
#define NM (NB * NK)   // 4096 total k rows

#define SCALE2LOG2E 2.8853900817779268f   // 2*log2(e)
#define LOG2E       1.4426950408889634f

// ---------------- scratch (static device globals; no cudaMalloc) ---------------
__device__ float g_qp[NB * NQ * DA];        // (q_proj + bias) * 2log2e
__device__ float g_kpt[DA * NM];            // k_proj transposed+scaled [a][m]
__device__ float g_sc[NB * NQ * NK];        // raw logits (-2 * sum v*sigmoid)

__device__ __forceinline__ float ex2(float x) {
    float r; asm("ex2.approx.f32 %0, %1;" : "=f"(r) : "f"(x)); return r;
}
__device__ __forceinline__ float rcp(float x) {
    float r; asm("rcp.approx.f32 %0, %1;" : "=f"(r) : "f"(x)); return r;
}

// ---------------- projection GEMM (reads W directly; double-buffered) ----------
// mode 0: g_qp[m][a]  = (X@W[:, :512]^T + bias) * SCALE    (m = b*NQ + q)
// mode 1: g_kpt[a][m] = (X@W[:, 512:]^T) * SCALE           (m = b*NK + k)
__global__ __launch_bounds__(256) void proj_gemm(
    const float* __restrict__ X, const float* __restrict__ W,
    const float* __restrict__ bias, int doff, int rows_per_b,
    const int* __restrict__ lens, int mode)
{
    const int a0 = blockIdx.x * 64;
    const int m0 = blockIdx.y * 64;
    const int b  = m0 / rows_per_b;
    if ((m0 % rows_per_b) >= lens[b]) return;   // whole tile masked

    __shared__ float As[2][16][68];
    __shared__ float Bs[2][16][68];
    const int tid = threadIdx.x;
    const int tx = tid & 15, ty = tid >> 4;

    const int ar = tid >> 2;          // A: m-row 0..63
    const int ac = (tid & 3) * 4;     // A: d-col group
    const int br = tid >> 2;          // B: a-row 0..63
    const int bc = (tid & 3) * 4;     // B: d-col group

    // prefetch first tiles into registers
    float4 a_reg = *(const float4*)(X + (size_t)(m0 + ar) * ND + ac);
    float4 b_reg = *(const float4*)(W + (size_t)(a0 + br) * 1024 + doff + bc);

    float acc[4][4] = {};
    int buf = 0;

    for (int d0 = 0; d0 < ND; d0 += 16) {
        // stage current registers into smem (transposed to [d][.] layout)
        As[buf][ac + 0][ar] = a_reg.x; As[buf][ac + 1][ar] = a_reg.y;
        As[buf][ac + 2][ar] = a_reg.z; As[buf][ac + 3][ar] = a_reg.w;
        Bs[buf][bc + 0][br] = b_reg.x; Bs[buf][bc + 1][br] = b_reg.y;
        Bs[buf][bc + 2][br] = b_reg.z; Bs[buf][bc + 3][br] = b_reg.w;
        __syncthreads();

        if (d0 + 16 < ND) {   // prefetch next tiles (latency hidden by compute)
            a_reg = *(const float4*)(X + (size_t)(m0 + ar) * ND + d0 + 16 + ac);
            b_reg = *(const float4*)(W + (size_t)(a0 + br) * 1024 + doff + d0 + 16 + bc);
        }

#pragma unroll
        for (int kk = 0; kk < 16; kk++) {
            float4 afv = *(const float4*)&As[buf][kk][ty * 4];
            float4 bfv = *(const float4*)&Bs[buf][kk][tx * 4];
            float aa[4] = {afv.x, afv.y, afv.z, afv.w};
            float bb[4] = {bfv.x, bfv.y, bfv.z, bfv.w};
#pragma unroll
            for (int i = 0; i < 4; i++)
#pragma unroll
                for (int j = 0; j < 4; j++)
                    acc[i][j] += aa[i] * bb[j];
        }
        buf ^= 1;
        // single sync per iter is safe: compute(i) precedes store(i+1) in
        // program order, and the sync after store(i+1) orders it vs others'
        // store into the buffer compute(i) was reading (2 iterations later).
    }

    if (mode == 0) {
        float badd[4];
        badd[0] = bias[a0 + tx * 4 + 0];
        badd[1] = bias[a0 + tx * 4 + 1];
        badd[2] = bias[a0 + tx * 4 + 2];
        badd[3] = bias[a0 + tx * 4 + 3];
#pragma unroll
        for (int i = 0; i < 4; i++) {
            const int m = m0 + ty * 4 + i;
            float4 o;
            o.x = (acc[i][0] + badd[0]) * SCALE2LOG2E;
            o.y = (acc[i][1] + badd[1]) * SCALE2LOG2E;
            o.z = (acc[i][2] + badd[2]) * SCALE2LOG2E;
            o.w = (acc[i][3] + badd[3]) * SCALE2LOG2E;
            *(float4*)(g_qp + (size_t)m * DA + a0 + tx * 4) = o;
        }
    } else {
#pragma unroll
        for (int j = 0; j < 4; j++) {
            const int a = a0 + tx * 4 + j;
            float4 o;
            o.x = acc[0][j] * SCALE2LOG2E;
            o.y = acc[1][j] * SCALE2LOG2E;
            o.z = acc[2][j] * SCALE2LOG2E;
            o.w = acc[3][j] * SCALE2LOG2E;
            *(float4*)(g_kpt + (size_t)a * NM + m0 + ty * 4) = o;
        }
    }
}

// ---------------- K1: logits. grid (NB, NQ/4, NK/64); thread = one (k, qi) -----
// logit = -2 * sum_a v_a * sigmoid-ish   (constant vsum shift dropped: softmax
// is shift-invariant). Software-pipelined kpt loads (cur/nxt ping-pong).
__global__ __launch_bounds__(256) void score_kernel(
    const float* __restrict__ vvec,
    const int* __restrict__ qlen_p, const int* __restrict__ klen_p)
{
    const int b  = blockIdx.x;
    const int q0 = blockIdx.y * 4;
    const int k0 = blockIdx.z * 64;
    if (q0 >= qlen_p[b] || k0 >= klen_p[b]) return;

    const int tid = threadIdx.x;
    const int kk = tid & 63;
    const int qi = tid >> 6;

    __shared__ float4 qsm[4][DA / 4];
    __shared__ float4 vsm[DA / 4];
    for (int i = tid; i < 4 * (DA / 4); i += 256)
        qsm[i >> 6][i & 63] =
            *(const float4*)(g_qp + (size_t)(b * NQ + q0 + (i >> 6)) * DA + (i & 63) * 4);
    for (int i = tid; i < DA / 4; i += 256)
        vsm[i] = *(const float4*)(vvec + i * 4);
    __syncthreads();

    const float* kpcol = g_kpt + (size_t)b * NK + k0 + kk;   // stride NM per a
    const float4* qrow = qsm[qi];

    float s = 0.f;
    float cur[8], nxt[8];
#pragma unroll
    for (int u = 0; u < 8; u++) cur[u] = kpcol[(size_t)u * NM];

#pragma unroll 2
    for (int a = 0; a < DA - 8; a += 8) {
#pragma unroll
        for (int u = 0; u < 8; u++)
            nxt[u] = kpcol[(size_t)(a + 8 + u) * NM];   // prefetch next group
#pragma unroll
        for (int g = 0; g < 2; g++) {
            const float4 qv = qrow[(a >> 2) + g];
            const float4 vv = vsm[(a >> 2) + g];
            float r0 = rcp(1.0f + ex2(qv.x + cur[g * 4 + 0]));
            float r1 = rcp(1.0f + ex2(qv.y + cur[g * 4 + 1]));
            float r2 = rcp(1.0f + ex2(qv.z + cur[g * 4 + 2]));
            float r3 = rcp(1.0f + ex2(qv.w + cur[g * 4 + 3]));
            s = fmaf(vv.x, r0, s);
            s = fmaf(vv.y, r1, s);
            s = fmaf(vv.z, r2, s);
            s = fmaf(vv.w, r3, s);
        }
#pragma unroll
        for (int u = 0; u < 8; u++) cur[u] = nxt[u];
    }
    // final group (a = DA-8)
#pragma unroll
    for (int g = 0; g < 2; g++) {
        const float4 qv = qrow[((DA - 8) >> 2) + g];
        const float4 vv = vsm[((DA - 8) >> 2) + g];
        float r0 = rcp(1.0f + ex2(qv.x + cur[g * 4 + 0]));
        float r1 = rcp(1.0f + ex2(qv.y + cur[g * 4 + 1]));
        float r2 = rcp(1.0f + ex2(qv.z + cur[g * 4 + 2]));
        float r3 = rcp(1.0f + ex2(qv.w + cur[g * 4 + 3]));
        s = fmaf(vv.x, r0, s);
        s = fmaf(vv.y, r1, s);
        s = fmaf(vv.z, r2, s);
        s = fmaf(vv.w, r3, s);
    }

    g_sc[(size_t)(b * NQ + q0 + qi) * NK + k0 + kk] = -2.0f * s;
}

// ---------------- K2: fused softmax + AV. grid (NB, NQ/4, ND/128) --------------
// Phase 1: softmax of the CTA's 4 rows into smem (masked rows -> probs = 1,
// Z sums to NK automatically). Phase 2: AV with probs broadcast from smem.
__global__ __launch_bounds__(256) void av_kernel(
    const float* __restrict__ kv,
    const int* __restrict__ qlen_p, const int* __restrict__ klen_p,
    float* __restrict__ out)
{
    const int b  = blockIdx.x;
    const int q0 = blockIdx.y * 4;
    const int dc = blockIdx.z;
    const int tid = threadIdx.x;
    const int w = tid >> 5, lane = tid & 31;
    const int qlen = qlen_p[b];
    const int klen = klen_p[b];

    __shared__ float  psm[NK * 4];       // [k][qi] probs, 8 KB
    __shared__ float  redm[4][2], reds[4][2];
    __shared__ float  izs[4];
    __shared__ float2 parts[3][4][64];   // kh 1..3 partials

    // ---- phase 1: softmax (warp = (row qi = w>>1, half h = w&1)) ---------------
    {
        const int qi = w >> 1, h = w & 1;
        const int q = q0 + qi;
        const bool masked = (q >= qlen);
        const float* row = g_sc + (size_t)(b * NQ + q) * NK + h * 256;

        float vals[8];
        float lmax = -1e30f;
        if (!masked) {
#pragma unroll
            for (int i = 0; i < 8; i++) {
                vals[i] = row[i * 32 + lane];
                const int k = h * 256 + i * 32 + lane;
                if (k < klen) lmax = fmaxf(lmax, vals[i]);
            }
        }
#pragma unroll
        for (int o = 16; o; o >>= 1)
            lmax = fmaxf(lmax, __shfl_xor_sync(0xffffffffu, lmax, o));
        if (lane == 0) redm[qi][h] = lmax;
        __syncthreads();

        const float m = fmaxf(redm[qi][0], redm[qi][1]);
        float lsum = 0.f;
#pragma unroll
        for (int i = 0; i < 8; i++) {
            const int k = h * 256 + i * 32 + lane;
            float e;
            if (masked)          e = 1.0f;            // uniform; Z sums to NK
            else if (k < klen)   e = ex2((vals[i] - m) * LOG2E);
            else                 e = 0.0f;
            psm[k * 4 + qi] = e;
            lsum += e;
        }
#pragma unroll
        for (int o = 16; o; o >>= 1)
            lsum += __shfl_xor_sync(0xffffffffu, lsum, o);
        if (lane == 0) reds[qi][h] = lsum;
        __syncthreads();
        if (tid < 4) izs[tid] = __fdividef(1.0f, reds[tid][0] + reds[tid][1]);
        __syncthreads();
    }

    // ---- phase 2: AV. thread = (dl: 2 d's, kh: k stride-4 split) ---------------
    const int dl = tid & 63, kh = tid >> 6;
    const int kmax = (qlen >= q0 + 4) ? klen : NK;   // tile w/ masked rows: all k
    const float2* kvp = (const float2*)(kv + (size_t)b * NK * ND) + dc * 64 + dl;

    float2 A0 = {0,0}, A1 = {0,0}, A2 = {0,0}, A3 = {0,0};
    int k = kh;
    for (; k + 4 < kmax; k += 8) {
        const float2 x0 = kvp[(size_t)k * (ND / 2)];
        const float2 x1 = kvp[(size_t)(k + 4) * (ND / 2)];
        const float4 p0 = *(const float4*)&psm[k * 4];
        const float4 p1 = *(const float4*)&psm[(k + 4) * 4];
        A0.x = fmaf(p0.x, x0.x, A0.x); A0.y = fmaf(p0.x, x0.y, A0.y);
        A1.x = fmaf(p0.y, x0.x, A1.x); A1.y = fmaf(p0.y, x0.y, A1.y);
        A2.x = fmaf(p0.z, x0.x, A2.x); A2.y = fmaf(p0.z, x0.y, A2.y);
        A3.x = fmaf(p0.w, x0.x, A3.x); A3.y = fmaf(p0.w, x0.y, A3.y);
        A0.x = fmaf(p1.x, x1.x, A0.x); A0.y = fmaf(p1.x, x1.y, A0.y);
        A1.x = fmaf(p1.y, x1.x, A1.x); A1.y = fmaf(p1.y, x1.y, A1.y);
        A2.x = fmaf(p1.z, x1.x, A2.x); A2.y = fmaf(p1.z, x1.y, A2.y);
        A3.x = fmaf(p1.w, x1.x, A3.x); A3.y = fmaf(p1.w, x1.y, A3.y);
    }
    for (; k < kmax; k += 4) {
        const float2 x = kvp[(size_t)k * (ND / 2)];
        const float4 p = *(const float4*)&psm[k * 4];
        A0.x = fmaf(p.x, x.x, A0.x); A0.y = fmaf(p.x, x.y, A0.y);
        A1.x = fmaf(p.y, x.x, A1.x); A1.y = fmaf(p.y, x.y, A1.y);
        A2.x = fmaf(p.z, x.x, A2.x); A2.y = fmaf(p.z, x.y, A2.y);
        A3.x = fmaf(p.w, x.x, A3.x); A3.y = fmaf(p.w, x.y, A3.y);
    }

    if (kh > 0) {
        parts[kh - 1][0][dl] = A0; parts[kh - 1][1][dl] = A1;
        parts[kh - 1][2][dl] = A2; parts[kh - 1][3][dl] = A3;
    }
    __syncthreads();
    if (kh == 0) {
        float2 acc[4] = {A0, A1, A2, A3};
#pragma unroll
        for (int qi = 0; qi < 4; qi++) {
#pragma unroll
            for (int p = 0; p < 3; p++) {
                acc[qi].x += parts[p][qi][dl].x;
                acc[qi].y += parts[p][qi][dl].y;
            }
            const float iz = izs[qi];
            float2 o = make_float2(acc[qi].x * iz, acc[qi].y * iz);
            ((float2*)(out + (size_t)(b * NQ + q0 + qi) * ND))[dc * 64 + dl] = o;
        }
    }
}

// ---------------- launch --------------------------------------------------------
extern "C" void kernel_launch(void* const* d_in, const int* in_sizes, int n_in,
                              void* d_out, int out_size)
{
    const float* query = (const float*)d_in[0];
    const float* kv    = (const float*)d_in[1];
    const float* W     = (const float*)d_in[2];
    const float* bias  = (const float*)d_in[3];
    const float* v     = (const float*)d_in[4];
    const int*   qlen  = (const int*)d_in[5];
    const int*   klen  = (const int*)d_in[6];
    float* out = (float*)d_out;

    proj_gemm<<<dim3(DA / 64, (NB * NQ) / 64), 256>>>(query, W, bias, 0,   NQ, qlen, 0);
    proj_gemm<<<dim3(DA / 64, (NB * NK) / 64), 256>>>(kv,    W, bias, 512, NK, klen, 1);
    score_kernel<<<dim3(NB, NQ / 4, NK / 64), 256>>>(v, qlen, klen);
    av_kernel<<<dim3(NB, NQ / 4, ND / 128), 256>>>(kv, qlen, klen, out);
}